// round 1
// baseline (speedup 1.0000x reference)
#include <cuda_runtime.h>
#include <math.h>

// Problem constants
#define BATCH    64
#define IN_CAPS  2048
#define IN_DIM   16
#define NUM_CAPS 32
#define OUT_DIM  16
#define JD       512            // NUM_CAPS * OUT_DIM
#define NIC      32             // i-chunks per batch in iter kernel
#define IC       (IN_CAPS/NIC)  // 64 i's per block
#define IG       4              // i's processed per barrier group

// Scratch (device globals: allocation-free per harness rules)
__device__ float g_uhat[(size_t)BATCH * IN_CAPS * JD];        // 256 MB
__device__ float g_logits[(size_t)BATCH * IN_CAPS * NUM_CAPS]; // 16 MB
__device__ float g_spart[(size_t)BATCH * NIC * JD];            // 4 MB
__device__ float g_out[(size_t)BATCH * JD];                    // 128 KB

// ---------------------------------------------------------------------------
// K1: u_hat[b,i,j,d] = sum_k W[i,j,d,k] * x[b,i,k]
// One block per i (2048 blocks, 512 threads). Thread t = j*16+d owns one W row
// (16 floats in regs); x[:,i,:] staged in smem; loop over b with broadcast LDS.
// Writes are coalesced: warp writes 128B contiguous per b.
// ---------------------------------------------------------------------------
__global__ __launch_bounds__(512) void uhat_kernel(
    const float* __restrict__ x, const float* __restrict__ W)
{
    const int i = blockIdx.x;
    const int t = threadIdx.x;          // 0..511  (= j*16 + d)

    __shared__ float4 xs[BATCH][4];     // 64 rows x 16 floats

    if (t < 256) {
        int b = t >> 2, q = t & 3;
        xs[b][q] = ((const float4*)(x + ((size_t)b * IN_CAPS + i) * IN_DIM))[q];
    }

    const float4* Wr = (const float4*)(W + ((size_t)i * JD + t) * IN_DIM);
    float4 w0 = Wr[0], w1 = Wr[1], w2 = Wr[2], w3 = Wr[3];

    __syncthreads();

    float* out = g_uhat + (size_t)i * JD + t;
    #pragma unroll 4
    for (int b = 0; b < BATCH; b++) {
        float4 a0 = xs[b][0], a1 = xs[b][1], a2 = xs[b][2], a3 = xs[b][3];
        float acc;
        acc = w0.x * a0.x;
        acc = fmaf(w0.y, a0.y, acc);
        acc = fmaf(w0.z, a0.z, acc);
        acc = fmaf(w0.w, a0.w, acc);
        acc = fmaf(w1.x, a1.x, acc);
        acc = fmaf(w1.y, a1.y, acc);
        acc = fmaf(w1.z, a1.z, acc);
        acc = fmaf(w1.w, a1.w, acc);
        acc = fmaf(w2.x, a2.x, acc);
        acc = fmaf(w2.y, a2.y, acc);
        acc = fmaf(w2.z, a2.z, acc);
        acc = fmaf(w2.w, a2.w, acc);
        acc = fmaf(w3.x, a3.x, acc);
        acc = fmaf(w3.y, a3.y, acc);
        acc = fmaf(w3.z, a3.z, acc);
        acc = fmaf(w3.w, a3.w, acc);
        out[(size_t)b * IN_CAPS * JD] = acc;
    }
}

// ---------------------------------------------------------------------------
// Fused routing iteration: per (b, i) compute agreement a_j = <u_hat, out_prev>,
// logits update, softmax over j, and accumulate c_j * u_hat into s partials.
// Grid: (NIC, BATCH), 256 threads. Thread t owns jd = t and jd = t+256.
// iter==0: c is exactly 1/32 (softmax of zeros) -> pure streaming sum.
// iter==1: logits = agreement(out0), written to g_logits.
// iter==2: logits = g_logits + agreement(out1).
// ---------------------------------------------------------------------------
__global__ __launch_bounds__(256) void iter_kernel(int iter)
{
    const int b  = blockIdx.y;
    const int ic = blockIdx.x;
    const int t  = threadIdx.x;          // 0..255
    const int i0 = ic * IC;

    __shared__ float out_s[JD];
    __shared__ float sm_a[IG * NUM_CAPS];
    __shared__ float sm_c[IG * NUM_CAPS];

    const float* uh = g_uhat + ((size_t)b * IN_CAPS + i0) * JD;
    float sacc1 = 0.f, sacc2 = 0.f;

    if (iter == 0) {
        #pragma unroll 8
        for (int g = 0; g < IC; g++) {
            sacc1 += uh[(size_t)g * JD + t];
            sacc2 += uh[(size_t)g * JD + t + 256];
        }
        sacc1 *= (1.0f / NUM_CAPS);
        sacc2 *= (1.0f / NUM_CAPS);
    } else {
        out_s[t]       = g_out[(size_t)b * JD + t];
        out_s[t + 256] = g_out[(size_t)b * JD + t + 256];
        __syncthreads();

        const int j1 = t >> 4;           // 0..15 ; second value is j1+16

        for (int gg = 0; gg < IC; gg += IG) {
            float v1[IG], v2[IG];
            #pragma unroll
            for (int g = 0; g < IG; g++) {
                v1[g] = uh[(size_t)(gg + g) * JD + t];
                v2[g] = uh[(size_t)(gg + g) * JD + t + 256];
            }
            #pragma unroll
            for (int g = 0; g < IG; g++) {
                float p1 = v1[g] * out_s[t];
                float p2 = v2[g] * out_s[t + 256];
                #pragma unroll
                for (int o = 8; o; o >>= 1) {
                    p1 += __shfl_xor_sync(0xffffffffu, p1, o);
                    p2 += __shfl_xor_sync(0xffffffffu, p2, o);
                }
                if ((t & 15) == 0) {
                    sm_a[g * NUM_CAPS + j1]      = p1;
                    sm_a[g * NUM_CAPS + j1 + 16] = p2;
                }
            }
            __syncthreads();

            // softmax for IG rows: warp g handles row gg+g, lane = j
            if (t < IG * 32) {
                int g  = t >> 5;
                int jj = t & 31;
                int ii = i0 + gg + g;
                float bv = sm_a[g * NUM_CAPS + jj];
                float* lg = g_logits + ((size_t)b * IN_CAPS + ii) * NUM_CAPS + jj;
                if (iter == 2) bv += *lg;
                else           *lg = bv;   // iter==1: persist logits for iter 2
                float m = bv;
                #pragma unroll
                for (int o = 16; o; o >>= 1)
                    m = fmaxf(m, __shfl_xor_sync(0xffffffffu, m, o));
                float e = __expf(bv - m);
                float ssum = e;
                #pragma unroll
                for (int o = 16; o; o >>= 1)
                    ssum += __shfl_xor_sync(0xffffffffu, ssum, o);
                sm_c[g * NUM_CAPS + jj] = e / ssum;
            }
            __syncthreads();

            #pragma unroll
            for (int g = 0; g < IG; g++) {
                sacc1 = fmaf(sm_c[g * NUM_CAPS + j1],      v1[g], sacc1);
                sacc2 = fmaf(sm_c[g * NUM_CAPS + 16 + j1], v2[g], sacc2);
            }
            // sm_a rewrite of next round is fenced by its following barrier;
            // sm_c reads here complete before next round's sm_c write barrier.
        }
    }

    float* sp = g_spart + ((size_t)b * NIC + ic) * JD;
    sp[t]       = sacc1;
    sp[t + 256] = sacc2;
}

// ---------------------------------------------------------------------------
// Reduce partials over NIC chunks, apply squash. 64 blocks x 512 threads.
// Thread t = j*16+d ; ||s_j||^2 via 16-lane butterfly.
// ---------------------------------------------------------------------------
__global__ __launch_bounds__(512) void squash_kernel(int final_out, float* __restrict__ dout)
{
    const int b = blockIdx.x;
    const int t = threadIdx.x;

    const float* sp = g_spart + (size_t)b * NIC * JD + t;
    float s = 0.f;
    #pragma unroll
    for (int p = 0; p < NIC; p++) s += sp[(size_t)p * JD];

    float s2 = s * s;
    #pragma unroll
    for (int o = 8; o; o >>= 1)
        s2 += __shfl_xor_sync(0xffffffffu, s2, o);

    float scale = s2 / ((1.0f + s2) * sqrtf(s2 + 1e-7f));
    float v = s * scale;

    if (final_out) dout[(size_t)b * JD + t] = v;
    else           g_out[(size_t)b * JD + t] = v;
}

// ---------------------------------------------------------------------------
extern "C" void kernel_launch(void* const* d_in, const int* in_sizes, int n_in,
                              void* d_out, int out_size)
{
    const float* x = (const float*)d_in[0];
    const float* W = (const float*)d_in[1];
    // Defensive: x has 2,097,152 elems, W has 16,777,216 — swap if order differs.
    if (in_sizes[0] == (int)((size_t)IN_CAPS * NUM_CAPS * IN_DIM * OUT_DIM)) {
        const float* tmp = x; x = W; W = tmp;
    }
    float* out = (float*)d_out;

    dim3 ig(NIC, BATCH);

    uhat_kernel<<<IN_CAPS, 512>>>(x, W);

    iter_kernel<<<ig, 256>>>(0);
    squash_kernel<<<BATCH, 512>>>(0, out);

    iter_kernel<<<ig, 256>>>(1);
    squash_kernel<<<BATCH, 512>>>(0, out);

    iter_kernel<<<ig, 256>>>(2);
    squash_kernel<<<BATCH, 512>>>(1, out);
}

// round 2
// speedup vs baseline: 1.5947x; 1.5947x over previous
#include <cuda_runtime.h>
#include <cuda_fp16.h>
#include <math.h>

// Problem constants
#define BATCH    64
#define IN_CAPS  2048
#define IN_DIM   16
#define NUM_CAPS 32
#define OUT_DIM  16
#define JD       512            // NUM_CAPS * OUT_DIM
#define NIC      32             // i-chunks per batch in iter kernel
#define IC       (IN_CAPS/NIC)  // 64 i's per block

// Scratch (device globals; allocation-free per harness rules)
__device__ __align__(16) __half g_uhat[(size_t)BATCH * IN_CAPS * JD];  // 128 MB, [b][i][j*16+d]
__device__ float g_spart[(size_t)BATCH * NIC * JD];  // 4 MB, d-major [b][ic][d*32+j]
__device__ float g_out0[(size_t)BATCH * JD];         // d-major [b][d*32+j]
__device__ float g_out1[(size_t)BATCH * JD];

// ---------------------------------------------------------------------------
// K1: u_hat[b,i,j,d] = sum_k W[i,j,d,k] * x[b,i,k]  -> fp16
// One block per i (2048 blocks, 512 threads). Thread t = j*16+d owns one W row
// in registers; x[:,i,:] staged in smem (broadcast LDS, conflict-free).
// ---------------------------------------------------------------------------
__global__ __launch_bounds__(512) void uhat_kernel(
    const float* __restrict__ x, const float* __restrict__ W)
{
    const int i = blockIdx.x;
    const int t = threadIdx.x;          // 0..511  (= j*16 + d)

    __shared__ float4 xs[BATCH][4];     // 64 rows x 16 floats

    if (t < 256) {
        int b = t >> 2, q = t & 3;
        xs[b][q] = ((const float4*)(x + ((size_t)b * IN_CAPS + i) * IN_DIM))[q];
    }

    const float4* Wr = (const float4*)(W + ((size_t)i * JD + t) * IN_DIM);
    float4 w0 = Wr[0], w1 = Wr[1], w2 = Wr[2], w3 = Wr[3];

    __syncthreads();

    __half* out = g_uhat + (size_t)i * JD + t;
    #pragma unroll 4
    for (int b = 0; b < BATCH; b++) {
        float4 a0 = xs[b][0], a1 = xs[b][1], a2 = xs[b][2], a3 = xs[b][3];
        float acc;
        acc = w0.x * a0.x;
        acc = fmaf(w0.y, a0.y, acc);
        acc = fmaf(w0.z, a0.z, acc);
        acc = fmaf(w0.w, a0.w, acc);
        acc = fmaf(w1.x, a1.x, acc);
        acc = fmaf(w1.y, a1.y, acc);
        acc = fmaf(w1.z, a1.z, acc);
        acc = fmaf(w1.w, a1.w, acc);
        acc = fmaf(w2.x, a2.x, acc);
        acc = fmaf(w2.y, a2.y, acc);
        acc = fmaf(w2.z, a2.z, acc);
        acc = fmaf(w2.w, a2.w, acc);
        acc = fmaf(w3.x, a3.x, acc);
        acc = fmaf(w3.y, a3.y, acc);
        acc = fmaf(w3.z, a3.z, acc);
        acc = fmaf(w3.w, a3.w, acc);
        out[(size_t)b * IN_CAPS * JD] = __float2half_rn(acc);
    }
}

// ---------------------------------------------------------------------------
// Fused routing iteration. Lane = j; each lane holds u_hat[b,i,lane,0:15] in
// registers (one 32B contiguous load). Agreement = 16 reg FMAs; softmax =
// one 32-lane butterfly per i per warp. No logits buffer:
//   iter1 logits = <u, out0>;  iter2 logits = <u, out0 + out1>.
// Grid (NIC, BATCH), 8 warps; warp w handles i = i0 + w, i0+w+8, ...
// ---------------------------------------------------------------------------
__global__ __launch_bounds__(256) void iter_kernel(int iter)
{
    const int b    = blockIdx.y;
    const int ic   = blockIdx.x;
    const int t    = threadIdx.x;
    const int w    = t >> 5;
    const int lane = t & 31;            // = j
    const int i0   = ic * IC;

    float vout[16];
    if (iter > 0) {
        #pragma unroll
        for (int d = 0; d < 16; d++) {
            float v = g_out0[(size_t)b * JD + d * 32 + lane];
            if (iter == 2) v += g_out1[(size_t)b * JD + d * 32 + lane];
            vout[d] = v;
        }
    }

    float acc[16];
    #pragma unroll
    for (int d = 0; d < 16; d++) acc[d] = 0.f;

    const __half* uhbase = g_uhat + ((size_t)b * IN_CAPS + i0) * JD + lane * 16;

    #pragma unroll 2
    for (int ii = w; ii < IC; ii += 8) {
        const __half* uh = uhbase + (size_t)ii * JD;
        uint4 r0 = *(const uint4*)uh;
        uint4 r1 = *(const uint4*)(uh + 8);
        float v[16];
        {
            float2 f;
            f = __half22float2(*(const __half2*)&r0.x); v[0]  = f.x; v[1]  = f.y;
            f = __half22float2(*(const __half2*)&r0.y); v[2]  = f.x; v[3]  = f.y;
            f = __half22float2(*(const __half2*)&r0.z); v[4]  = f.x; v[5]  = f.y;
            f = __half22float2(*(const __half2*)&r0.w); v[6]  = f.x; v[7]  = f.y;
            f = __half22float2(*(const __half2*)&r1.x); v[8]  = f.x; v[9]  = f.y;
            f = __half22float2(*(const __half2*)&r1.y); v[10] = f.x; v[11] = f.y;
            f = __half22float2(*(const __half2*)&r1.z); v[12] = f.x; v[13] = f.y;
            f = __half22float2(*(const __half2*)&r1.w); v[14] = f.x; v[15] = f.y;
        }

        if (iter == 0) {
            #pragma unroll
            for (int d = 0; d < 16; d++) acc[d] += v[d];
        } else {
            float a = v[0] * vout[0];
            #pragma unroll
            for (int d = 1; d < 16; d++) a = fmaf(v[d], vout[d], a);

            float m = a;
            #pragma unroll
            for (int o = 16; o; o >>= 1)
                m = fmaxf(m, __shfl_xor_sync(0xffffffffu, m, o));
            float e = __expf(a - m);
            float s = e;
            #pragma unroll
            for (int o = 16; o; o >>= 1)
                s += __shfl_xor_sync(0xffffffffu, s, o);
            float c = e / s;

            #pragma unroll
            for (int d = 0; d < 16; d++) acc[d] = fmaf(c, v[d], acc[d]);
        }
    }

    if (iter == 0) {
        #pragma unroll
        for (int d = 0; d < 16; d++) acc[d] *= (1.0f / NUM_CAPS);
    }

    // Cross-warp reduce (d-major in smem: conflict-free writes and reads)
    __shared__ float red[8][JD];
    #pragma unroll
    for (int d = 0; d < 16; d++) red[w][d * 32 + lane] = acc[d];
    __syncthreads();

    float s1 = 0.f, s2 = 0.f;
    #pragma unroll
    for (int ww = 0; ww < 8; ww++) {
        s1 += red[ww][t];
        s2 += red[ww][t + 256];
    }
    float* sp = g_spart + ((size_t)b * NIC + ic) * JD;
    sp[t]       = s1;
    sp[t + 256] = s2;
}

// ---------------------------------------------------------------------------
// Reduce partials over NIC chunks + squash. d-major positions: t = d*32 + j.
// which: 0 -> g_out0, 1 -> g_out1, 2 -> dout (permuted to [b][j][d]).
// ---------------------------------------------------------------------------
__global__ __launch_bounds__(512) void squash_kernel(int which, float* __restrict__ dout)
{
    const int b = blockIdx.x;
    const int t = threadIdx.x;

    const float* sp = g_spart + (size_t)b * NIC * JD + t;
    float s = 0.f;
    #pragma unroll
    for (int p = 0; p < NIC; p++) s += sp[(size_t)p * JD];

    __shared__ float s2s[NUM_CAPS];
    if (t < NUM_CAPS) s2s[t] = 0.f;
    __syncthreads();
    atomicAdd(&s2s[t & 31], s * s);
    __syncthreads();

    float s2 = s2s[t & 31];
    float scale = s2 / ((1.0f + s2) * sqrtf(s2 + 1e-7f));
    float v = s * scale;

    if (which == 2)      dout[(size_t)b * JD + (t & 31) * 16 + (t >> 5)] = v;
    else if (which == 0) g_out0[(size_t)b * JD + t] = v;
    else                 g_out1[(size_t)b * JD + t] = v;
}

// ---------------------------------------------------------------------------
extern "C" void kernel_launch(void* const* d_in, const int* in_sizes, int n_in,
                              void* d_out, int out_size)
{
    const float* x = (const float*)d_in[0];
    const float* W = (const float*)d_in[1];
    if (in_sizes[0] == (int)((size_t)IN_CAPS * NUM_CAPS * IN_DIM * OUT_DIM)) {
        const float* tmp = x; x = W; W = tmp;
    }
    float* out = (float*)d_out;

    dim3 ig(NIC, BATCH);

    uhat_kernel<<<IN_CAPS, 512>>>(x, W);

    iter_kernel<<<ig, 256>>>(0);
    squash_kernel<<<BATCH, 512>>>(0, out);   // -> g_out0

    iter_kernel<<<ig, 256>>>(1);
    squash_kernel<<<BATCH, 512>>>(1, out);   // -> g_out1

    iter_kernel<<<ig, 256>>>(2);
    squash_kernel<<<BATCH, 512>>>(2, out);   // -> dout
}